// round 16
// baseline (speedup 1.0000x reference)
#include <cuda_runtime.h>

// Problem constants (fixed by the reference build)
#define Bn 4
#define Cn 32
#define Ln 256
#define Mn 256
#define Fn 8
#define Nw 64

typedef unsigned long long u64;

__device__ __forceinline__ u64 pack2(float lo, float hi) {
    u64 r;
    asm("mov.b64 %0, {%1, %2};" : "=l"(r) : "f"(lo), "f"(hi));
    return r;
}
__device__ __forceinline__ void ffma2(u64& d, u64 a, u64 b) {
    asm("fma.rn.f32x2 %0, %1, %2, %0;" : "+l"(d) : "l"(a), "l"(b));
}
__device__ __forceinline__ float2 unpack2(u64 v) {
    float2 r;
    asm("mov.b64 {%0, %1}, %2;" : "=f"(r.x), "=f"(r.y) : "l"(v));
    return r;
}

// CTA: 128 threads = (l, b-pair, m-half). Thread t owns:
//   b  = b0 + (t>>6)        (1 of the 2 b's)
//   fh = (t>>5)&1           (half of the f's: 4 f's)
//   m  = 128*mh + 4*(t&31) .. +3   (4 m's, float4 x loads)
// Per c: 3 LDS.128 (weights) + 2 LDG.128 (x) + 32 FFMA2.
// All hot-path addressing in int32 (max index < 2^26) to cut register pairs.
__global__ __launch_bounds__(128, 7)
void sphereconv_kernel(const float* __restrict__ xr,
                       const float* __restrict__ xi,
                       const float* __restrict__ wr,
                       const float* __restrict__ wi,
                       float* __restrict__ out)
{
    // Layout [c][f]: 16B-aligned groups of 4 floats per (c, f-half)
    __shared__ __align__(16) float s_wr [Cn * Fn];   // 1 KB
    __shared__ __align__(16) float s_wi [Cn * Fn];   // 1 KB
    __shared__ __align__(16) float s_nwi[Cn * Fn];   // 1 KB (pre-negated wi)

    const int l  = blockIdx.x;          // 0..255
    const int bp = blockIdx.y;          // 0..1
    const int mh = blockIdx.z;          // 0..1
    const int t  = threadIdx.x;         // 0..127
    const int b  = (bp << 1) + (t >> 6);
    const int fh = (t >> 5) & 1;        // f-half
    const int mq = t & 31;              // m-quad within half
    const int m0 = (mh << 7) + (mq << 2);

    // ---- Phase 1: interpolate weights for this l (F*C = 256, two per thread) ----
    {
        float tt = ((float)l / (float)(Ln - 1)) * (float)(Nw - 1);
        int lo = (int)tt;                       // tt >= 0 -> trunc == floor
        lo = lo > Nw - 2 ? Nw - 2 : lo;
        float frac = tt - (float)lo;
        #pragma unroll
        for (int e = t; e < Fn * Cn; e += 128) {
            int f = e >> 5, c = e & 31;
            int base = (f * Cn + c) * Nw;       // w shape (F, C, N, 1)
            float wre = wr[base + lo] * (1.0f - frac) + wr[base + lo + 1] * frac;
            float wim = wi[base + lo] * (1.0f - frac) + wi[base + lo + 1] * frac;
            s_wr [c * Fn + f] = wre;
            s_wi [c * Fn + f] = wim;
            s_nwi[c * Fn + f] = -wim;
        }
    }
    __syncthreads();

    const int strideC4 = (Ln * Mn) / 4;                 // 16384 float4's
    const int xbase4   = b * Cn * strideC4 + (l * Mn + m0) / 4;
    const float4* __restrict__ xr4 = (const float4*)xr + xbase4;
    const float4* __restrict__ xi4 = (const float4*)xi + xbase4;

    // Accumulators: [mm][pp] -> f32x2 over (f_even, f_odd) of local pair pp
    u64 ar[4][2], ai[4][2];
    #pragma unroll
    for (int mm = 0; mm < 4; mm++) {
        ar[mm][0] = 0ULL; ar[mm][1] = 0ULL;
        ai[mm][0] = 0ULL; ai[mm][1] = 0ULL;
    }

    // Rolling double buffer of float4 x chunks (1 c each)
    float4 bufR[2], bufI[2];
    bufR[0] = __ldg(xr4);
    bufI[0] = __ldg(xi4);
    bufR[1] = __ldg(xr4 + strideC4);
    bufI[1] = __ldg(xi4 + strideC4);

    const int wofs = fh << 2;   // float offset of this thread's 4 f's in a c row

    #pragma unroll
    for (int c = 0; c < Cn; c++) {
        const int s = c & 1;
        const float4 xrv = bufR[s];
        const float4 xiv = bufI[s];
        if (c + 2 < Cn) {
            bufR[s] = __ldg(xr4 + (c + 2) * strideC4);
            bufI[s] = __ldg(xi4 + (c + 2) * strideC4);
        }

        // 3x LDS.128 broadcast: {w_f0..w_f3} for this f-half
        const ulonglong2 wwr = *(const ulonglong2*)(s_wr  + c * Fn + wofs);
        const ulonglong2 wwi = *(const ulonglong2*)(s_wi  + c * Fn + wofs);
        const ulonglong2 wwn = *(const ulonglong2*)(s_nwi + c * Fn + wofs);

        #pragma unroll
        for (int mm = 0; mm < 4; mm++) {
            const float xrs = (&xrv.x)[mm];
            const float xis = (&xiv.x)[mm];
            const u64 xq2 = pack2(xrs, xrs);
            const u64 xj2 = pack2(xis, xis);

            ffma2(ar[mm][0], wwr.x, xq2);   // +wr*xr
            ffma2(ar[mm][0], wwn.x, xj2);   // -wi*xi
            ffma2(ai[mm][0], wwr.x, xj2);   // +wr*xi
            ffma2(ai[mm][0], wwi.x, xq2);   // +wi*xr
            ffma2(ar[mm][1], wwr.y, xq2);
            ffma2(ar[mm][1], wwn.y, xj2);
            ffma2(ai[mm][1], wwr.y, xj2);
            ffma2(ai[mm][1], wwi.y, xq2);
        }
    }

    // ---- Epilogue: mean over C, scale sqrt(1+l), relu real part, store ----
    const float sc = sqrtf(1.0f + (float)l) * (1.0f / (float)Cn);
    const int lm      = Ln * Mn;                  // 65536
    const int partOff = Bn * Fn * lm;             // 16.8M < 2^31 as int

    #pragma unroll
    for (int pp = 0; pp < 2; pp++) {
        const int pg     = (fh << 1) + pp;        // global f-pair index 0..3
        const int f_even = pg << 1;
        const int base   = ((b * Fn + f_even) * Ln + l) * Mn + m0;

        float4 vre, vro, vie, vio;                // even-f / odd-f, real / imag
        #pragma unroll
        for (int mm = 0; mm < 4; mm++) {
            const float2 r2 = unpack2(ar[mm][pp]);
            const float2 i2 = unpack2(ai[mm][pp]);
            (&vre.x)[mm] = fmaxf(r2.x * sc, 0.0f);
            (&vro.x)[mm] = fmaxf(r2.y * sc, 0.0f);
            (&vie.x)[mm] = i2.x * sc;
            (&vio.x)[mm] = i2.y * sc;
        }
        *(float4*)(out + base)                = vre;   // f_even, real
        *(float4*)(out + base + lm)           = vro;   // f_odd,  real
        *(float4*)(out + base + partOff)      = vie;   // f_even, imag
        *(float4*)(out + base + partOff + lm) = vio;   // f_odd,  imag
    }
}

extern "C" void kernel_launch(void* const* d_in, const int* in_sizes, int n_in,
                              void* d_out, int out_size) {
    const float* xr = (const float*)d_in[0];
    const float* xi = (const float*)d_in[1];
    const float* wr = (const float*)d_in[2];
    const float* wi = (const float*)d_in[3];
    float* out = (float*)d_out;

    dim3 grid(Ln, Bn / 2, 2);   // (l, b-pair, m-half) = 1024 CTAs of 128 threads
    sphereconv_kernel<<<grid, 128>>>(xr, xi, wr, wi, out);
}